// round 10
// baseline (speedup 1.0000x reference)
#include <cuda_runtime.h>
#include <cuda_bf16.h>
#include <cstdint>

#define D 128
#define NMAX 50000
#define EMAX 600000
#define LMAX 5
#define SCAN_B 256
#define NBLK ((NMAX + SCAN_B - 1) / SCAN_B)   // 196

// ---------------- device scratch (no allocation allowed) ----------------
__device__ float g_buf[NMAX * D];           // ping-pong activations
__device__ float g_inv[NMAX];               // 1/max(deg,1)
__device__ int   g_degi[NMAX];
__device__ int   g_rowptr[NMAX + 1];
__device__ int   g_cursor[NMAX];
__device__ int   g_tmp[NMAX];               // block-local inclusive scans
__device__ int   g_bsum[NBLK + 1];
__device__ int   g_srcs[EMAX];              // CSR: src node per (dst-sorted) edge
// weights pre-split (hi/lo bf16), transposed to [n][k], pre-swizzled:
// [layer][phase][split] blocks of 16384 bf16 (32KB each); phase0=Wl, phase1=Wr
__device__ __nv_bfloat16 g_Bsw[LMAX * 2 * 2 * 16384];

// Bank-conflict-free swizzle for [row][k] bf16 tiles, 256B/row (128 k).
__device__ __forceinline__ uint32_t swa(int r, int k) {
    return (uint32_t)(r * 256 + ((((k >> 3) ^ (r & 7)) << 4)) + ((k & 7) << 1));
}

__device__ __forceinline__ uint32_t smem_u32(const void* p) {
    uint32_t a;
    asm("{ .reg .u64 t; cvta.to.shared.u64 t, %1; cvt.u32.u64 %0, t; }" : "=r"(a) : "l"(p));
    return a;
}

__device__ __forceinline__ uint32_t pack_bf16x2(float a, float b) {
    __nv_bfloat162 t = __floats2bfloat162_rn(a, b);
    return *reinterpret_cast<uint32_t*>(&t);
}

__device__ __forceinline__ void ldsm_x4(uint32_t addr, uint32_t& r0, uint32_t& r1,
                                        uint32_t& r2, uint32_t& r3) {
    asm volatile("ldmatrix.sync.aligned.m8n8.x4.shared.b16 {%0,%1,%2,%3}, [%4];"
                 : "=r"(r0), "=r"(r1), "=r"(r2), "=r"(r3) : "r"(addr));
}

__device__ __forceinline__ void mma_bf16(float* c, uint32_t a0, uint32_t a1,
                                         uint32_t a2, uint32_t a3,
                                         uint32_t b0, uint32_t b1) {
    asm volatile(
        "mma.sync.aligned.m16n8k16.row.col.f32.bf16.bf16.f32 "
        "{%0,%1,%2,%3}, {%4,%5,%6,%7}, {%8,%9}, {%0,%1,%2,%3};"
        : "+f"(c[0]), "+f"(c[1]), "+f"(c[2]), "+f"(c[3])
        : "r"(a0), "r"(a1), "r"(a2), "r"(a3), "r"(b0), "r"(b1));
}

#define CP_ASYNC16(dst, src) \
    asm volatile("cp.async.cg.shared.global [%0], [%1], 16;" :: "r"(dst), "l"(src) : "memory")
#define CP_COMMIT() asm volatile("cp.async.commit_group;" ::: "memory")
#define CP_WAIT0()  asm volatile("cp.async.wait_group 0;" ::: "memory")

// warp-local dtype detect: int64 indices in [0,50000) -> high words all zero.
__device__ __forceinline__ int warp_is64(const int* ei32) {
    int lane = threadIdx.x & 31;
    int v = ei32[2 * lane + 1];
    return __all_sync(0xffffffffu, v == 0);
}

// ---------------- CSR build ----------------
__global__ void k_count(const void* ei, int E) {
    int is64 = warp_is64((const int*)ei);
    int i = blockIdx.x * blockDim.x + threadIdx.x;
    if (i >= E) return;
    int d = is64 ? (int)((const long long*)ei)[(long long)E + i]
                 : ((const int*)ei)[(long long)E + i];
    atomicAdd(&g_degi[d], 1);
}

__device__ __forceinline__ int block_incl_scan(int v, int* warp_s) {
    int lane = threadIdx.x & 31, wid = threadIdx.x >> 5;
    #pragma unroll
    for (int off = 1; off < 32; off <<= 1) {
        int t = __shfl_up_sync(0xffffffffu, v, off);
        if (lane >= off) v += t;
    }
    if (lane == 31) warp_s[wid] = v;
    __syncthreads();
    if (wid == 0) {
        int w = (lane < (int)(blockDim.x >> 5)) ? warp_s[lane] : 0;
        #pragma unroll
        for (int off = 1; off < 32; off <<= 1) {
            int t = __shfl_up_sync(0xffffffffu, w, off);
            if (lane >= off) w += t;
        }
        warp_s[lane] = w;
    }
    __syncthreads();
    if (wid > 0) v += warp_s[wid - 1];
    return v;
}

__global__ void k_scan1(int n) {
    __shared__ int ws[32];
    int i = blockIdx.x * SCAN_B + threadIdx.x;
    int v = (i < n) ? g_degi[i] : 0;
    int incl = block_incl_scan(v, ws);
    if (i < n) g_tmp[i] = incl;
    if (threadIdx.x == SCAN_B - 1) g_bsum[blockIdx.x] = incl;
}
__global__ void k_scan3(int n, int E, int nb) {
    __shared__ int red[SCAN_B / 32];
    int tid = threadIdx.x, lane = tid & 31, wid = tid >> 5;
    int bid = blockIdx.x;
    int v = (tid < bid && tid < nb) ? g_bsum[tid] : 0;
    #pragma unroll
    for (int off = 16; off > 0; off >>= 1) v += __shfl_down_sync(0xffffffffu, v, off);
    if (lane == 0) red[wid] = v;
    __syncthreads();
    if (tid == 0) {
        int s = 0;
        #pragma unroll
        for (int w = 0; w < SCAN_B / 32; w++) s += red[w];
        red[0] = s;
    }
    __syncthreads();
    int boff = red[0];
    int i = bid * SCAN_B + tid;
    if (i < n) {
        int dg = g_degi[i];
        int excl = g_tmp[i] - dg + boff;
        g_rowptr[i] = excl;
        g_cursor[i] = excl;
        g_inv[i] = 1.0f / fmaxf((float)dg, 1.0f);
    }
    if (i == 0) g_rowptr[n] = E;
}

__global__ void k_fill(const void* ei, int E) {
    int is64 = warp_is64((const int*)ei);
    int i = blockIdx.x * blockDim.x + threadIdx.x;
    if (i >= E) return;
    int s, d;
    if (is64) {
        s = (int)((const long long*)ei)[i];
        d = (int)((const long long*)ei)[(long long)E + i];
    } else {
        s = ((const int*)ei)[i];
        d = ((const int*)ei)[(long long)E + i];
    }
    int pos = atomicAdd(&g_cursor[d], 1);
    g_srcs[pos] = s;
}

// ---------------- weight prep: split bf16 hi/lo, transpose to [n][k], swizzle ---
__global__ void k_prep_w(const float* __restrict__ Wl, const float* __restrict__ Wr, int L) {
    int idx = blockIdx.x * blockDim.x + threadIdx.x;
    if (idx >= (L << 15)) return;          // L*2*128*128
    int k  = idx & 127;
    int nn = (idx >> 7) & 127;
    int ph = (idx >> 14) & 1;
    int l  = idx >> 15;
    float w = (ph == 0) ? Wl[((size_t)l * D + k) * D + nn]
                        : Wr[((size_t)l * D + k) * D + nn];
    __nv_bfloat16 h = __float2bfloat16(w);
    float r = w - __bfloat162float(h);
    size_t base = ((size_t)l * 2 + ph) * 2 * 16384;   // bf16 elements
    uint32_t off = swa(nn, k) >> 1;                   // bf16 index within 32KB tile
    g_Bsw[base + off] = h;
    g_Bsw[base + 16384 + off] = __float2bfloat16(r);
}

// ---------------- warp-specialized SAGE layer: producer gather + mma GEMM -----
// 384 threads: warps 0-7 compute, warps 8-11 gather this tile's 128 CSR rows
// straight into the phase-0 A smem tile (no global aggr round-trip).
// Compute runs phase 1 (x@Wr) first, overlapping the gather; handoff via one
// __syncthreads; then phase 0 (aggr@Wl). fp32 accum; bf16 hi/lo 3-pass split.
// SMEM: A1 64KB | A0 64KB | B 64KB | bias  = ~192.5KB, 1 CTA/SM.
__global__ __launch_bounds__(384, 1)
void k_layer(const float* __restrict__ x_in, const float* __restrict__ bias,
             float* __restrict__ out, int n, int layer, int do_relu) {
    extern __shared__ char sm[];
    char*  smA1  = sm;                        // x tile: hi 32KB + lo 32KB
    char*  smA0  = sm + 65536;                // aggr tile: hi + lo
    float* sbias = (float*)(sm + 196608);
    uint32_t sbA1 = smem_u32(smA1);
    uint32_t sbA0 = smem_u32(smA0);
    uint32_t sbB  = smem_u32(sm + 131072);

    int tid = threadIdx.x, wid = tid >> 5, l = tid & 31;
    int row0 = blockIdx.x * 128;
    int mw = (wid & 3) * 32;            // compute warp M offset
    int nw = (wid >> 2) * 64;           // compute warp N offset (wid<8)

    // B1 (= Wr, phase 1) prefetch by compute threads
    if (tid < 256) {
        const char* b1 = (const char*)(g_Bsw + ((size_t)layer * 2 + 1) * 2 * 16384);
        #pragma unroll 4
        for (int i = tid; i < 4096; i += 256)
            CP_ASYNC16(sbB + i * 16, b1 + (size_t)i * 16);
    }
    CP_COMMIT();

    if (tid < 128) sbias[tid] = bias[tid];

    float acc[2][8][4];
    #pragma unroll
    for (int mt = 0; mt < 2; mt++)
        #pragma unroll
        for (int nt = 0; nt < 8; nt++)
            #pragma unroll
            for (int q = 0; q < 4; q++) acc[mt][nt][q] = 0.f;

    if (wid < 8) {
        // ---- compute warps: produce A1 (x rows), then phase 1 passes ----
        {
            int k0 = l * 4;
            #pragma unroll 4
            for (int rr = 0; rr < 16; rr++) {
                int r = wid * 16 + rr;
                int grow = row0 + r;
                float4 v = make_float4(0.f, 0.f, 0.f, 0.f);
                if (grow < n) v = ((const float4*)(x_in + (size_t)grow * D))[l];
                float h0 = __bfloat162float(__float2bfloat16(v.x));
                float h1 = __bfloat162float(__float2bfloat16(v.y));
                float h2 = __bfloat162float(__float2bfloat16(v.z));
                float h3 = __bfloat162float(__float2bfloat16(v.w));
                uint2 hi = make_uint2(pack_bf16x2(h0, h1), pack_bf16x2(h2, h3));
                uint2 lo = make_uint2(pack_bf16x2(v.x - h0, v.y - h1),
                                      pack_bf16x2(v.z - h2, v.w - h3));
                uint32_t off = swa(r, k0);
                *(uint2*)(smA1 + off)         = hi;
                *(uint2*)(smA1 + 32768 + off) = lo;
            }
        }
        CP_WAIT0();                                   // B1 landed
        asm volatile("bar.sync 1, 256;" ::: "memory");  // compute warps only

        #pragma unroll
        for (int pass = 0; pass < 3; pass++) {
            uint32_t aB = sbA1 + (pass == 1 ? 32768u : 0u);
            uint32_t bP = sbB  + (pass == 2 ? 32768u : 0u);
            #pragma unroll
            for (int ks = 0; ks < 8; ks++) {
                int kbA = ks * 16 + ((l >> 4) << 3);
                uint32_t afr[2][4];
                #pragma unroll
                for (int mt = 0; mt < 2; mt++) {
                    uint32_t addr = aB + swa(mw + mt * 16 + (l & 15), kbA);
                    ldsm_x4(addr, afr[mt][0], afr[mt][1], afr[mt][2], afr[mt][3]);
                }
                int kbB = ks * 16 + (((l >> 3) & 1) << 3);
                #pragma unroll
                for (int g2 = 0; g2 < 4; g2++) {
                    int nn = nw + g2 * 16 + (l & 7) + ((l >> 4) << 3);
                    uint32_t addr = bP + swa(nn, kbB);
                    uint32_t b0, b1, b2, b3;
                    ldsm_x4(addr, b0, b1, b2, b3);
                    #pragma unroll
                    for (int mt = 0; mt < 2; mt++) {
                        mma_bf16(acc[mt][2 * g2 + 0], afr[mt][0], afr[mt][1],
                                 afr[mt][2], afr[mt][3], b0, b1);
                        mma_bf16(acc[mt][2 * g2 + 1], afr[mt][0], afr[mt][1],
                                 afr[mt][2], afr[mt][3], b2, b3);
                    }
                }
            }
        }
    } else {
        // ---- producer warps (8-11): CSR gather-mean -> A0 smem tile ----
        int pw = wid - 8;              // 0..3, handles tile rows [pw*32, pw*32+32)
        for (int g = 0; g < 8; g++) {
            int r0 = pw * 32 + g * 4;
            float4 a4[4]; int p[4], e[4]; float iv[4];
            #pragma unroll
            for (int i = 0; i < 4; i++) {
                int grow = row0 + r0 + i;
                a4[i] = make_float4(0.f, 0.f, 0.f, 0.f);
                if (grow < n) {
                    p[i] = g_rowptr[grow]; e[i] = g_rowptr[grow + 1];
                    iv[i] = g_inv[grow];
                } else { p[i] = 0; e[i] = 0; iv[i] = 1.f; }
            }
            int mx = 0;
            #pragma unroll
            for (int i = 0; i < 4; i++) { int c = e[i] - p[i]; if (c > mx) mx = c; }
            for (int t = 0; t < mx; t++) {
                #pragma unroll
                for (int i = 0; i < 4; i++) {
                    if (p[i] + t < e[i]) {
                        int s = g_srcs[p[i] + t];
                        float4 v = ((const float4*)(x_in + (size_t)s * D))[l];
                        a4[i].x += v.x; a4[i].y += v.y; a4[i].z += v.z; a4[i].w += v.w;
                    }
                }
            }
            #pragma unroll
            for (int i = 0; i < 4; i++) {
                float4 v = a4[i];
                v.x *= iv[i]; v.y *= iv[i]; v.z *= iv[i]; v.w *= iv[i];
                float h0 = __bfloat162float(__float2bfloat16(v.x));
                float h1 = __bfloat162float(__float2bfloat16(v.y));
                float h2 = __bfloat162float(__float2bfloat16(v.z));
                float h3 = __bfloat162float(__float2bfloat16(v.w));
                uint2 hi = make_uint2(pack_bf16x2(h0, h1), pack_bf16x2(h2, h3));
                uint2 lo = make_uint2(pack_bf16x2(v.x - h0, v.y - h1),
                                      pack_bf16x2(v.z - h2, v.w - h3));
                uint32_t off = swa(r0 + i, l * 4);
                *(uint2*)(smA0 + off)         = hi;
                *(uint2*)(smA0 + 32768 + off) = lo;
            }
        }
    }

    __syncthreads();   // A0 ready, phase-1 B reads done

    // B0 (= Wl, phase 0) load into the B buffer, all 384 threads
    {
        const char* b0 = (const char*)(g_Bsw + ((size_t)layer * 2 + 0) * 2 * 16384);
        for (int i = tid; i < 4096; i += 384)
            CP_ASYNC16(sbB + i * 16, b0 + (size_t)i * 16);
    }
    CP_COMMIT();
    CP_WAIT0();
    __syncthreads();

    if (wid < 8) {
        #pragma unroll
        for (int pass = 0; pass < 3; pass++) {
            uint32_t aB = sbA0 + (pass == 1 ? 32768u : 0u);
            uint32_t bP = sbB  + (pass == 2 ? 32768u : 0u);
            #pragma unroll
            for (int ks = 0; ks < 8; ks++) {
                int kbA = ks * 16 + ((l >> 4) << 3);
                uint32_t afr[2][4];
                #pragma unroll
                for (int mt = 0; mt < 2; mt++) {
                    uint32_t addr = aB + swa(mw + mt * 16 + (l & 15), kbA);
                    ldsm_x4(addr, afr[mt][0], afr[mt][1], afr[mt][2], afr[mt][3]);
                }
                int kbB = ks * 16 + (((l >> 3) & 1) << 3);
                #pragma unroll
                for (int g2 = 0; g2 < 4; g2++) {
                    int nn = nw + g2 * 16 + (l & 7) + ((l >> 4) << 3);
                    uint32_t addr = bP + swa(nn, kbB);
                    uint32_t b0, b1, b2, b3;
                    ldsm_x4(addr, b0, b1, b2, b3);
                    #pragma unroll
                    for (int mt = 0; mt < 2; mt++) {
                        mma_bf16(acc[mt][2 * g2 + 0], afr[mt][0], afr[mt][1],
                                 afr[mt][2], afr[mt][3], b0, b1);
                        mma_bf16(acc[mt][2 * g2 + 1], afr[mt][0], afr[mt][1],
                                 afr[mt][2], afr[mt][3], b2, b3);
                    }
                }
            }
        }

        // epilogue: D fragment layout (m16n8): rows g, g+8; cols 2t, 2t+1
        int g = l >> 2, t2 = (l & 3) * 2;
        #pragma unroll
        for (int mt = 0; mt < 2; mt++) {
            #pragma unroll
            for (int nt = 0; nt < 8; nt++) {
                int col = nw + nt * 8 + t2;
                float b0 = sbias[col], b1 = sbias[col + 1];
                int r1 = row0 + mw + mt * 16 + g;
                int r2 = r1 + 8;
                float o0 = acc[mt][nt][0] + b0, o1 = acc[mt][nt][1] + b1;
                float o2 = acc[mt][nt][2] + b0, o3 = acc[mt][nt][3] + b1;
                if (do_relu) {
                    o0 = fmaxf(o0, 0.f); o1 = fmaxf(o1, 0.f);
                    o2 = fmaxf(o2, 0.f); o3 = fmaxf(o3, 0.f);
                }
                if (r1 < n) *(float2*)(out + (size_t)r1 * D + col) = make_float2(o0, o1);
                if (r2 < n) *(float2*)(out + (size_t)r2 * D + col) = make_float2(o2, o3);
            }
        }
    }
}

// ---------------- host launcher ----------------
extern "C" void kernel_launch(void* const* d_in, const int* in_sizes, int n_in,
                              void* d_out, int out_size) {
    const float* x  = (const float*)d_in[0];
    const void*  ei = d_in[1];
    const float* Wl = (const float*)d_in[2];
    const float* bl = (const float*)d_in[3];
    const float* Wr = (const float*)d_in[4];
    float* out = (float*)d_out;

    int n = in_sizes[0] / D;
    int E = in_sizes[1] / 2;
    int L = in_sizes[2] / (D * D);

    void* pbuf = nullptr;
    cudaGetSymbolAddress(&pbuf, g_buf);
    float* buf = (float*)pbuf;
    void* pdeg = nullptr;
    cudaGetSymbolAddress(&pdeg, g_degi);

    const int LAYER_SMEM = 196608 + 512;
    cudaFuncSetAttribute(k_layer, cudaFuncAttributeMaxDynamicSharedMemorySize, LAYER_SMEM);

    // CSR build (once per call; dtype detect inlined per-warp in count/fill)
    cudaMemsetAsync(pdeg, 0, (size_t)n * sizeof(int));
    k_count<<<(E + 255) / 256, 256>>>(ei, E);
    int nb_s = (n + SCAN_B - 1) / SCAN_B;
    k_scan1<<<nb_s, SCAN_B>>>(n);
    k_scan3<<<nb_s, SCAN_B>>>(n, E, nb_s);
    k_fill<<<(E + 255) / 256, 256>>>(ei, E);

    // weight split/transpose/swizzle (once per call)
    int wtot = L << 15;
    k_prep_w<<<(wtot + 255) / 256, 256>>>(Wl, Wr, L);

    int nb = (n + 127) / 128;
    const float* cur = x;
    for (int l = 0; l < L; l++) {
        float* o = (l % 2 == 0) ? out : buf;   // L=5 -> final layer lands in out
        k_layer<<<nb, 384, LAYER_SMEM>>>(cur, bl + (size_t)l * D, o, n, l, l < L - 1 ? 1 : 0);
        cur = o;
    }
    if (cur != out) {
        cudaMemcpyAsync(out, cur, (size_t)n * D * sizeof(float), cudaMemcpyDeviceToDevice);
    }
}

// round 11
// speedup vs baseline: 2.2589x; 2.2589x over previous
#include <cuda_runtime.h>
#include <cuda_bf16.h>
#include <cstdint>

#define D 128
#define NMAX 50000
#define EMAX 600000
#define LMAX 5
#define SCAN_B 256
#define NBLK ((NMAX + SCAN_B - 1) / SCAN_B)   // 196

// ---------------- device scratch (no allocation allowed) ----------------
__device__ float g_aggr[NMAX * D];          // mean-aggregated features
__device__ float g_buf[NMAX * D];           // ping-pong activations
__device__ float g_inv[NMAX];               // 1/max(deg,1)
__device__ int   g_degi[NMAX];
__device__ int   g_rowptr[NMAX + 1];
__device__ int   g_cursor[NMAX];
__device__ int   g_tmp[NMAX];               // block-local inclusive scans
__device__ int   g_bsum[NBLK + 1];
__device__ int   g_srcs[EMAX];              // CSR: src node per (dst-sorted) edge
// weights pre-split (hi/lo bf16), transposed to [n][k], pre-swizzled:
// [layer][phase][split] blocks of 16384 bf16 (32KB each)
__device__ __nv_bfloat16 g_Bsw[LMAX * 2 * 2 * 16384];

// Bank-conflict-free swizzle for [row][k] bf16 tiles, 256B/row (128 k).
__device__ __forceinline__ uint32_t swa(int r, int k) {
    return (uint32_t)(r * 256 + ((((k >> 3) ^ (r & 7)) << 4)) + ((k & 7) << 1));
}

__device__ __forceinline__ uint32_t smem_u32(const void* p) {
    uint32_t a;
    asm("{ .reg .u64 t; cvta.to.shared.u64 t, %1; cvt.u32.u64 %0, t; }" : "=r"(a) : "l"(p));
    return a;
}

__device__ __forceinline__ uint32_t pack_bf16x2(float a, float b) {
    __nv_bfloat162 t = __floats2bfloat162_rn(a, b);
    return *reinterpret_cast<uint32_t*>(&t);
}

__device__ __forceinline__ void ldsm_x4(uint32_t addr, uint32_t& r0, uint32_t& r1,
                                        uint32_t& r2, uint32_t& r3) {
    asm volatile("ldmatrix.sync.aligned.m8n8.x4.shared.b16 {%0,%1,%2,%3}, [%4];"
                 : "=r"(r0), "=r"(r1), "=r"(r2), "=r"(r3) : "r"(addr));
}

__device__ __forceinline__ void mma_bf16(float* c, uint32_t a0, uint32_t a1,
                                         uint32_t a2, uint32_t a3,
                                         uint32_t b0, uint32_t b1) {
    asm volatile(
        "mma.sync.aligned.m16n8k16.row.col.f32.bf16.bf16.f32 "
        "{%0,%1,%2,%3}, {%4,%5,%6,%7}, {%8,%9}, {%0,%1,%2,%3};"
        : "+f"(c[0]), "+f"(c[1]), "+f"(c[2]), "+f"(c[3])
        : "r"(a0), "r"(a1), "r"(a2), "r"(a3), "r"(b0), "r"(b1));
}

#define CP_ASYNC16(dst, src) \
    asm volatile("cp.async.cg.shared.global [%0], [%1], 16;" :: "r"(dst), "l"(src) : "memory")
#define CP_COMMIT() asm volatile("cp.async.commit_group;" ::: "memory")
#define CP_WAIT1()  asm volatile("cp.async.wait_group 1;" ::: "memory")
#define CP_WAIT0()  asm volatile("cp.async.wait_group 0;" ::: "memory")

// warp-local dtype detect: int64 indices in [0,50000) -> high words all zero.
__device__ __forceinline__ int warp_is64(const int* ei32) {
    int lane = threadIdx.x & 31;
    int v = ei32[2 * lane + 1];
    return __all_sync(0xffffffffu, v == 0);
}

// ---------------- CSR build ----------------
__global__ void k_count(const void* ei, int E) {
    int is64 = warp_is64((const int*)ei);
    int i = blockIdx.x * blockDim.x + threadIdx.x;
    if (i >= E) return;
    int d = is64 ? (int)((const long long*)ei)[(long long)E + i]
                 : ((const int*)ei)[(long long)E + i];
    atomicAdd(&g_degi[d], 1);
}

__device__ __forceinline__ int block_incl_scan(int v, int* warp_s) {
    int lane = threadIdx.x & 31, wid = threadIdx.x >> 5;
    #pragma unroll
    for (int off = 1; off < 32; off <<= 1) {
        int t = __shfl_up_sync(0xffffffffu, v, off);
        if (lane >= off) v += t;
    }
    if (lane == 31) warp_s[wid] = v;
    __syncthreads();
    if (wid == 0) {
        int w = (lane < (int)(blockDim.x >> 5)) ? warp_s[lane] : 0;
        #pragma unroll
        for (int off = 1; off < 32; off <<= 1) {
            int t = __shfl_up_sync(0xffffffffu, w, off);
            if (lane >= off) w += t;
        }
        warp_s[lane] = w;
    }
    __syncthreads();
    if (wid > 0) v += warp_s[wid - 1];
    return v;
}

__global__ void k_scan1(int n) {
    __shared__ int ws[32];
    int i = blockIdx.x * SCAN_B + threadIdx.x;
    int v = (i < n) ? g_degi[i] : 0;
    int incl = block_incl_scan(v, ws);
    if (i < n) g_tmp[i] = incl;
    if (threadIdx.x == SCAN_B - 1) g_bsum[blockIdx.x] = incl;
}
__global__ void k_scan3(int n, int E, int nb) {
    __shared__ int red[SCAN_B / 32];
    int tid = threadIdx.x, lane = tid & 31, wid = tid >> 5;
    int bid = blockIdx.x;
    int v = (tid < bid && tid < nb) ? g_bsum[tid] : 0;
    #pragma unroll
    for (int off = 16; off > 0; off >>= 1) v += __shfl_down_sync(0xffffffffu, v, off);
    if (lane == 0) red[wid] = v;
    __syncthreads();
    if (tid == 0) {
        int s = 0;
        #pragma unroll
        for (int w = 0; w < SCAN_B / 32; w++) s += red[w];
        red[0] = s;
    }
    __syncthreads();
    int boff = red[0];
    int i = bid * SCAN_B + tid;
    if (i < n) {
        int dg = g_degi[i];
        int excl = g_tmp[i] - dg + boff;
        g_rowptr[i] = excl;
        g_cursor[i] = excl;
        g_inv[i] = 1.0f / fmaxf((float)dg, 1.0f);
    }
    if (i == 0) g_rowptr[n] = E;
}

__global__ void k_fill(const void* ei, int E) {
    int is64 = warp_is64((const int*)ei);
    int i = blockIdx.x * blockDim.x + threadIdx.x;
    if (i >= E) return;
    int s, d;
    if (is64) {
        s = (int)((const long long*)ei)[i];
        d = (int)((const long long*)ei)[(long long)E + i];
    } else {
        s = ((const int*)ei)[i];
        d = ((const int*)ei)[(long long)E + i];
    }
    int pos = atomicAdd(&g_cursor[d], 1);
    g_srcs[pos] = s;
}

// ---------------- mean aggregation: warp per node (CSR gather) ----------------
__global__ void k_gather(const float* __restrict__ x, int n) {
    int w = (blockIdx.x * blockDim.x + threadIdx.x) >> 5;
    int lane = threadIdx.x & 31;
    if (w >= n) return;
    int b = g_rowptr[w], e = g_rowptr[w + 1];
    float4 acc = make_float4(0.f, 0.f, 0.f, 0.f);
    for (int j = b; j < e; j++) {
        int s = g_srcs[j];  // warp-uniform
        float4 v = ((const float4*)(x + (size_t)s * D))[lane];
        acc.x += v.x; acc.y += v.y; acc.z += v.z; acc.w += v.w;
    }
    float iv = g_inv[w];
    acc.x *= iv; acc.y *= iv; acc.z *= iv; acc.w *= iv;
    ((float4*)(g_aggr + (size_t)w * D))[lane] = acc;
}

// ---------------- weight prep: split bf16 hi/lo, transpose to [n][k], swizzle ---
__global__ void k_prep_w(const float* __restrict__ Wl, const float* __restrict__ Wr, int L) {
    int idx = blockIdx.x * blockDim.x + threadIdx.x;
    if (idx >= (L << 15)) return;          // L*2*128*128
    int k  = idx & 127;
    int nn = (idx >> 7) & 127;
    int ph = (idx >> 14) & 1;
    int l  = idx >> 15;
    float w = (ph == 0) ? Wl[((size_t)l * D + k) * D + nn]
                        : Wr[((size_t)l * D + k) * D + nn];
    __nv_bfloat16 h = __float2bfloat16(w);
    float r = w - __bfloat162float(h);
    size_t base = ((size_t)l * 2 + ph) * 2 * 16384;   // bf16 elements
    uint32_t off = swa(nn, k) >> 1;                   // bf16 index within 32KB tile
    g_Bsw[base + off] = h;
    g_Bsw[base + 16384 + off] = __float2bfloat16(r);
}

// ---------------- fused SAGE layer GEMM: ldmatrix + mma.sync bf16 3-pass -------
// out[128-tile] = aggr@Wl + x@Wr + b (+relu), fp32 accum in registers.
// SMEM: A hi/lo 64KB + B0 64KB + B1 64KB + bias = ~197KB, 1 CTA/SM.
// Both phases' B tiles prefetched with cp.async at kernel start.
__global__ __launch_bounds__(256, 1)
void k_gemm(const float* __restrict__ x_in, const float* __restrict__ bias,
            float* __restrict__ out, int n, int layer, int do_relu) {
    extern __shared__ char sm[];
    char*  smA   = sm;                        // A hi (32KB) + A lo (32KB)
    float* sbias = (float*)(sm + 196608);
    uint32_t sbA = smem_u32(smA);
    uint32_t sbB0 = smem_u32(sm + 65536);
    uint32_t sbB1 = smem_u32(sm + 131072);

    int tid = threadIdx.x, wid = tid >> 5, l = tid & 31;
    int row0 = blockIdx.x * 128;
    int mw = (wid & 3) * 32;            // warp M offset
    int nw = (wid >> 2) * 64;           // warp N offset

    // prefetch both phases' pre-swizzled B (64KB each) via cp.async
    {
        const char* b0 = (const char*)(g_Bsw + ((size_t)layer * 2 + 0) * 2 * 16384);
        const char* b1 = (const char*)(g_Bsw + ((size_t)layer * 2 + 1) * 2 * 16384);
        #pragma unroll 4
        for (int i = tid; i < 4096; i += 256)
            CP_ASYNC16(sbB0 + i * 16, b0 + (size_t)i * 16);
        CP_COMMIT();
        #pragma unroll 4
        for (int i = tid; i < 4096; i += 256)
            CP_ASYNC16(sbB1 + i * 16, b1 + (size_t)i * 16);
        CP_COMMIT();
    }

    if (tid < 128) sbias[tid] = bias[tid];

    float acc[2][8][4];
    #pragma unroll
    for (int mt = 0; mt < 2; mt++)
        #pragma unroll
        for (int nt = 0; nt < 8; nt++)
            #pragma unroll
            for (int q = 0; q < 4; q++) acc[mt][nt][q] = 0.f;

    for (int ph = 0; ph < 2; ph++) {
        if (ph) __syncthreads();        // all warps done reading A of phase 0

        // A: load fp32 rows, split bf16 hi/lo, swizzled STS (conflict-free)
        {
            const float* amat = ph ? x_in : g_aggr;
            int k0 = l * 4;
            #pragma unroll 4
            for (int rr = 0; rr < 16; rr++) {
                int r = wid * 16 + rr;
                int grow = row0 + r;
                float4 v = make_float4(0.f, 0.f, 0.f, 0.f);
                if (grow < n) v = ((const float4*)(amat + (size_t)grow * D))[l];
                float h0 = __bfloat162float(__float2bfloat16(v.x));
                float h1 = __bfloat162float(__float2bfloat16(v.y));
                float h2 = __bfloat162float(__float2bfloat16(v.z));
                float h3 = __bfloat162float(__float2bfloat16(v.w));
                uint2 hi = make_uint2(pack_bf16x2(h0, h1), pack_bf16x2(h2, h3));
                uint2 lo = make_uint2(pack_bf16x2(v.x - h0, v.y - h1),
                                      pack_bf16x2(v.z - h2, v.w - h3));
                uint32_t off = swa(r, k0);
                *(uint2*)(smA + off)         = hi;
                *(uint2*)(smA + 32768 + off) = lo;
            }
        }
        if (ph == 0) CP_WAIT1();        // B0 landed
        else         CP_WAIT0();        // B1 landed
        __syncthreads();

        uint32_t bB = ph ? sbB1 : sbB0;
        // 3 split passes: (Ah,Bh), (Al,Bh), (Ah,Bl) accumulate into acc
        #pragma unroll
        for (int pass = 0; pass < 3; pass++) {
            uint32_t aB = sbA + (pass == 1 ? 32768u : 0u);
            uint32_t bP = bB + (pass == 2 ? 32768u : 0u);
            #pragma unroll
            for (int ks = 0; ks < 8; ks++) {
                int kbA = ks * 16 + ((l >> 4) << 3);
                uint32_t afr[2][4];
                #pragma unroll
                for (int mt = 0; mt < 2; mt++) {
                    uint32_t addr = aB + swa(mw + mt * 16 + (l & 15), kbA);
                    ldsm_x4(addr, afr[mt][0], afr[mt][1], afr[mt][2], afr[mt][3]);
                }
                int kbB = ks * 16 + (((l >> 3) & 1) << 3);
                #pragma unroll
                for (int g2 = 0; g2 < 4; g2++) {
                    int nn = nw + g2 * 16 + (l & 7) + ((l >> 4) << 3);
                    uint32_t addr = bP + swa(nn, kbB);
                    uint32_t b0, b1, b2, b3;
                    ldsm_x4(addr, b0, b1, b2, b3);
                    #pragma unroll
                    for (int mt = 0; mt < 2; mt++) {
                        mma_bf16(acc[mt][2 * g2 + 0], afr[mt][0], afr[mt][1],
                                 afr[mt][2], afr[mt][3], b0, b1);
                        mma_bf16(acc[mt][2 * g2 + 1], afr[mt][0], afr[mt][1],
                                 afr[mt][2], afr[mt][3], b2, b3);
                    }
                }
            }
        }
    }

    // epilogue: D fragment layout (m16n8): rows g, g+8; cols 2t, 2t+1
    int g = l >> 2, t2 = (l & 3) * 2;
    #pragma unroll
    for (int mt = 0; mt < 2; mt++) {
        #pragma unroll
        for (int nt = 0; nt < 8; nt++) {
            int col = nw + nt * 8 + t2;
            float b0 = sbias[col], b1 = sbias[col + 1];
            int r1 = row0 + mw + mt * 16 + g;
            int r2 = r1 + 8;
            float o0 = acc[mt][nt][0] + b0, o1 = acc[mt][nt][1] + b1;
            float o2 = acc[mt][nt][2] + b0, o3 = acc[mt][nt][3] + b1;
            if (do_relu) {
                o0 = fmaxf(o0, 0.f); o1 = fmaxf(o1, 0.f);
                o2 = fmaxf(o2, 0.f); o3 = fmaxf(o3, 0.f);
            }
            if (r1 < n) *(float2*)(out + (size_t)r1 * D + col) = make_float2(o0, o1);
            if (r2 < n) *(float2*)(out + (size_t)r2 * D + col) = make_float2(o2, o3);
        }
    }
}

// ---------------- host launcher ----------------
extern "C" void kernel_launch(void* const* d_in, const int* in_sizes, int n_in,
                              void* d_out, int out_size) {
    const float* x  = (const float*)d_in[0];
    const void*  ei = d_in[1];
    const float* Wl = (const float*)d_in[2];
    const float* bl = (const float*)d_in[3];
    const float* Wr = (const float*)d_in[4];
    float* out = (float*)d_out;

    int n = in_sizes[0] / D;
    int E = in_sizes[1] / 2;
    int L = in_sizes[2] / (D * D);

    void* pbuf = nullptr;
    cudaGetSymbolAddress(&pbuf, g_buf);
    float* buf = (float*)pbuf;
    void* pdeg = nullptr;
    cudaGetSymbolAddress(&pdeg, g_degi);

    const int GEMM_SMEM = 196608 + 512;
    cudaFuncSetAttribute(k_gemm, cudaFuncAttributeMaxDynamicSharedMemorySize, GEMM_SMEM);

    // CSR build (once per call; dtype detect inlined per-warp in count/fill)
    cudaMemsetAsync(pdeg, 0, (size_t)n * sizeof(int));
    k_count<<<(E + 255) / 256, 256>>>(ei, E);
    int nb_s = (n + SCAN_B - 1) / SCAN_B;
    k_scan1<<<nb_s, SCAN_B>>>(n);
    k_scan3<<<nb_s, SCAN_B>>>(n, E, nb_s);
    k_fill<<<(E + 255) / 256, 256>>>(ei, E);

    // weight split/transpose/swizzle (once per call)
    int wtot = L << 15;
    k_prep_w<<<(wtot + 255) / 256, 256>>>(Wl, Wr, L);

    int nb = (n + 127) / 128;
    const float* cur = x;
    for (int l = 0; l < L; l++) {
        k_gather<<<(n + 7) / 8, 256>>>(cur, n);
        float* o = (l % 2 == 0) ? out : buf;   // L=5 -> final layer lands in out
        k_gemm<<<nb, 256, GEMM_SMEM>>>(cur, bl + (size_t)l * D, o, n, l, l < L - 1 ? 1 : 0);
        cur = o;
    }
    if (cur != out) {
        cudaMemcpyAsync(out, cur, (size_t)n * D * sizeof(float), cudaMemcpyDeviceToDevice);
    }
}

// round 12
// speedup vs baseline: 2.3216x; 1.0278x over previous
#include <cuda_runtime.h>
#include <cuda_bf16.h>
#include <cstdint>

#define D 128
#define NMAX 50000
#define EMAX 600000
#define LMAX 5
#define SCAN_B 256
#define NBLK ((NMAX + SCAN_B - 1) / SCAN_B)   // 196

// ---------------- device scratch (no allocation allowed) ----------------
__device__ float g_aggr[NMAX * D];          // mean-aggregated features
__device__ float g_buf[NMAX * D];           // ping-pong activations
__device__ float g_inv[NMAX];               // 1/max(deg,1)
__device__ int   g_degi[NMAX];
__device__ int   g_rowptr[NMAX + 1];
__device__ int   g_cursor[NMAX];
__device__ int   g_tmp[NMAX];               // block-local inclusive scans
__device__ int   g_bsum[NBLK + 1];
__device__ int   g_srcs[EMAX];              // CSR: src node per (dst-sorted) edge
// weights pre-split (hi/lo bf16), transposed to [n][k], pre-swizzled:
// [layer][phase][split] blocks of 16384 bf16 (32KB each)
__device__ __nv_bfloat16 g_Bsw[LMAX * 2 * 2 * 16384];

// Bank-conflict-free swizzle for [row][k] bf16 tiles, 256B/row (128 k).
__device__ __forceinline__ uint32_t swa(int r, int k) {
    return (uint32_t)(r * 256 + ((((k >> 3) ^ (r & 7)) << 4)) + ((k & 7) << 1));
}

__device__ __forceinline__ uint32_t smem_u32(const void* p) {
    uint32_t a;
    asm("{ .reg .u64 t; cvta.to.shared.u64 t, %1; cvt.u32.u64 %0, t; }" : "=r"(a) : "l"(p));
    return a;
}

__device__ __forceinline__ uint32_t pack_bf16x2(float a, float b) {
    __nv_bfloat162 t = __floats2bfloat162_rn(a, b);
    return *reinterpret_cast<uint32_t*>(&t);
}

__device__ __forceinline__ void ldsm_x4(uint32_t addr, uint32_t& r0, uint32_t& r1,
                                        uint32_t& r2, uint32_t& r3) {
    asm volatile("ldmatrix.sync.aligned.m8n8.x4.shared.b16 {%0,%1,%2,%3}, [%4];"
                 : "=r"(r0), "=r"(r1), "=r"(r2), "=r"(r3) : "r"(addr));
}

__device__ __forceinline__ void mma_bf16(float* c, const uint32_t* a,
                                         uint32_t b0, uint32_t b1) {
    asm volatile(
        "mma.sync.aligned.m16n8k16.row.col.f32.bf16.bf16.f32 "
        "{%0,%1,%2,%3}, {%4,%5,%6,%7}, {%8,%9}, {%0,%1,%2,%3};"
        : "+f"(c[0]), "+f"(c[1]), "+f"(c[2]), "+f"(c[3])
        : "r"(a[0]), "r"(a[1]), "r"(a[2]), "r"(a[3]), "r"(b0), "r"(b1));
}

#define CP_ASYNC16(dst, src) \
    asm volatile("cp.async.cg.shared.global [%0], [%1], 16;" :: "r"(dst), "l"(src) : "memory")
#define CP_COMMIT() asm volatile("cp.async.commit_group;" ::: "memory")
#define CP_WAIT1()  asm volatile("cp.async.wait_group 1;" ::: "memory")
#define CP_WAIT0()  asm volatile("cp.async.wait_group 0;" ::: "memory")

// warp-local dtype detect: int64 indices in [0,50000) -> high words all zero.
__device__ __forceinline__ int warp_is64(const int* ei32) {
    int lane = threadIdx.x & 31;
    int v = ei32[2 * lane + 1];
    return __all_sync(0xffffffffu, v == 0);
}

// ---------------- CSR build ----------------
__global__ void k_count(const void* ei, int E) {
    int is64 = warp_is64((const int*)ei);
    int i = blockIdx.x * blockDim.x + threadIdx.x;
    if (i >= E) return;
    int d = is64 ? (int)((const long long*)ei)[(long long)E + i]
                 : ((const int*)ei)[(long long)E + i];
    atomicAdd(&g_degi[d], 1);
}

__device__ __forceinline__ int block_incl_scan(int v, int* warp_s) {
    int lane = threadIdx.x & 31, wid = threadIdx.x >> 5;
    #pragma unroll
    for (int off = 1; off < 32; off <<= 1) {
        int t = __shfl_up_sync(0xffffffffu, v, off);
        if (lane >= off) v += t;
    }
    if (lane == 31) warp_s[wid] = v;
    __syncthreads();
    if (wid == 0) {
        int w = (lane < (int)(blockDim.x >> 5)) ? warp_s[lane] : 0;
        #pragma unroll
        for (int off = 1; off < 32; off <<= 1) {
            int t = __shfl_up_sync(0xffffffffu, w, off);
            if (lane >= off) w += t;
        }
        warp_s[lane] = w;
    }
    __syncthreads();
    if (wid > 0) v += warp_s[wid - 1];
    return v;
}

__global__ void k_scan1(int n) {
    __shared__ int ws[32];
    int i = blockIdx.x * SCAN_B + threadIdx.x;
    int v = (i < n) ? g_degi[i] : 0;
    int incl = block_incl_scan(v, ws);
    if (i < n) g_tmp[i] = incl;
    if (threadIdx.x == SCAN_B - 1) g_bsum[blockIdx.x] = incl;
}
__global__ void k_scan3(int n, int E, int nb) {
    __shared__ int red[SCAN_B / 32];
    int tid = threadIdx.x, lane = tid & 31, wid = tid >> 5;
    int bid = blockIdx.x;
    int v = (tid < bid && tid < nb) ? g_bsum[tid] : 0;
    #pragma unroll
    for (int off = 16; off > 0; off >>= 1) v += __shfl_down_sync(0xffffffffu, v, off);
    if (lane == 0) red[wid] = v;
    __syncthreads();
    if (tid == 0) {
        int s = 0;
        #pragma unroll
        for (int w = 0; w < SCAN_B / 32; w++) s += red[w];
        red[0] = s;
    }
    __syncthreads();
    int boff = red[0];
    int i = bid * SCAN_B + tid;
    if (i < n) {
        int dg = g_degi[i];
        int excl = g_tmp[i] - dg + boff;
        g_rowptr[i] = excl;
        g_cursor[i] = excl;
        g_inv[i] = 1.0f / fmaxf((float)dg, 1.0f);
    }
    if (i == 0) g_rowptr[n] = E;
}

__global__ void k_fill(const void* ei, int E) {
    int is64 = warp_is64((const int*)ei);
    int i = blockIdx.x * blockDim.x + threadIdx.x;
    if (i >= E) return;
    int s, d;
    if (is64) {
        s = (int)((const long long*)ei)[i];
        d = (int)((const long long*)ei)[(long long)E + i];
    } else {
        s = ((const int*)ei)[i];
        d = ((const int*)ei)[(long long)E + i];
    }
    int pos = atomicAdd(&g_cursor[d], 1);
    g_srcs[pos] = s;
}

// ---------------- mean aggregation: warp per node (CSR gather) ----------------
__global__ void k_gather(const float* __restrict__ x, int n) {
    int w = (blockIdx.x * blockDim.x + threadIdx.x) >> 5;
    int lane = threadIdx.x & 31;
    if (w >= n) return;
    int b = g_rowptr[w], e = g_rowptr[w + 1];
    float4 acc = make_float4(0.f, 0.f, 0.f, 0.f);
    for (int j = b; j < e; j++) {
        int s = g_srcs[j];  // warp-uniform
        float4 v = ((const float4*)(x + (size_t)s * D))[lane];
        acc.x += v.x; acc.y += v.y; acc.z += v.z; acc.w += v.w;
    }
    float iv = g_inv[w];
    acc.x *= iv; acc.y *= iv; acc.z *= iv; acc.w *= iv;
    ((float4*)(g_aggr + (size_t)w * D))[lane] = acc;
}

// ---------------- weight prep: split bf16 hi/lo, transpose to [n][k], swizzle ---
__global__ void k_prep_w(const float* __restrict__ Wl, const float* __restrict__ Wr, int L) {
    int idx = blockIdx.x * blockDim.x + threadIdx.x;
    if (idx >= (L << 15)) return;          // L*2*128*128
    int k  = idx & 127;
    int nn = (idx >> 7) & 127;
    int ph = (idx >> 14) & 1;
    int l  = idx >> 15;
    float w = (ph == 0) ? Wl[((size_t)l * D + k) * D + nn]
                        : Wr[((size_t)l * D + k) * D + nn];
    __nv_bfloat16 h = __float2bfloat16(w);
    float r = w - __bfloat162float(h);
    size_t base = ((size_t)l * 2 + ph) * 2 * 16384;   // bf16 elements
    uint32_t off = swa(nn, k) >> 1;                   // bf16 index within 32KB tile
    g_Bsw[base + off] = h;
    g_Bsw[base + 16384 + off] = __float2bfloat16(r);
}

// ---------------- fused SAGE layer GEMM: ldmatrix + mma.sync bf16 3-pass -------
// out[128-tile] = aggr@Wl + x@Wr + b (+relu), fp32 accum in registers.
// ks-major mainloop: per ks, load Ah/Al/Bh/Bl fragments ONCE (12 ldsm.x4),
// then fire all 48 MMAs from registers — 33% less smem crossbar traffic than
// the pass-major 3x re-read form.
__global__ __launch_bounds__(256, 1)
void k_gemm(const float* __restrict__ x_in, const float* __restrict__ bias,
            float* __restrict__ out, int n, int layer, int do_relu) {
    extern __shared__ char sm[];
    char*  smA   = sm;                        // A hi (32KB) + A lo (32KB)
    float* sbias = (float*)(sm + 196608);
    uint32_t sbA = smem_u32(smA);
    uint32_t sbB0 = smem_u32(sm + 65536);
    uint32_t sbB1 = smem_u32(sm + 131072);

    int tid = threadIdx.x, wid = tid >> 5, l = tid & 31;
    int row0 = blockIdx.x * 128;
    int mw = (wid & 3) * 32;            // warp M offset
    int nw = (wid >> 2) * 64;           // warp N offset

    // prefetch both phases' pre-swizzled B (64KB each) via cp.async
    {
        const char* b0 = (const char*)(g_Bsw + ((size_t)layer * 2 + 0) * 2 * 16384);
        const char* b1 = (const char*)(g_Bsw + ((size_t)layer * 2 + 1) * 2 * 16384);
        #pragma unroll 4
        for (int i = tid; i < 4096; i += 256)
            CP_ASYNC16(sbB0 + i * 16, b0 + (size_t)i * 16);
        CP_COMMIT();
        #pragma unroll 4
        for (int i = tid; i < 4096; i += 256)
            CP_ASYNC16(sbB1 + i * 16, b1 + (size_t)i * 16);
        CP_COMMIT();
    }

    if (tid < 128) sbias[tid] = bias[tid];

    float acc[2][8][4];
    #pragma unroll
    for (int mt = 0; mt < 2; mt++)
        #pragma unroll
        for (int nt = 0; nt < 8; nt++)
            #pragma unroll
            for (int q = 0; q < 4; q++) acc[mt][nt][q] = 0.f;

    for (int ph = 0; ph < 2; ph++) {
        if (ph) __syncthreads();        // all warps done reading A of phase 0

        // A: load fp32 rows, split bf16 hi/lo, swizzled STS (conflict-free)
        {
            const float* amat = ph ? x_in : g_aggr;
            int k0 = l * 4;
            #pragma unroll 4
            for (int rr = 0; rr < 16; rr++) {
                int r = wid * 16 + rr;
                int grow = row0 + r;
                float4 v = make_float4(0.f, 0.f, 0.f, 0.f);
                if (grow < n) v = ((const float4*)(amat + (size_t)grow * D))[l];
                float h0 = __bfloat162float(__float2bfloat16(v.x));
                float h1 = __bfloat162float(__float2bfloat16(v.y));
                float h2 = __bfloat162float(__float2bfloat16(v.z));
                float h3 = __bfloat162float(__float2bfloat16(v.w));
                uint2 hi = make_uint2(pack_bf16x2(h0, h1), pack_bf16x2(h2, h3));
                uint2 lo = make_uint2(pack_bf16x2(v.x - h0, v.y - h1),
                                      pack_bf16x2(v.z - h2, v.w - h3));
                uint32_t off = swa(r, k0);
                *(uint2*)(smA + off)         = hi;
                *(uint2*)(smA + 32768 + off) = lo;
            }
        }
        if (ph == 0) CP_WAIT1();        // B0 landed
        else         CP_WAIT0();        // B1 landed
        __syncthreads();

        uint32_t bB = ph ? sbB1 : sbB0;
        #pragma unroll
        for (int ks = 0; ks < 8; ks++) {
            // ---- load ALL fragments for this ks once ----
            int kbA = ks * 16 + ((l >> 4) << 3);
            uint32_t ah[2][4], al[2][4];
            #pragma unroll
            for (int mt = 0; mt < 2; mt++) {
                uint32_t addr = sbA + swa(mw + mt * 16 + (l & 15), kbA);
                ldsm_x4(addr, ah[mt][0], ah[mt][1], ah[mt][2], ah[mt][3]);
                ldsm_x4(addr + 32768u, al[mt][0], al[mt][1], al[mt][2], al[mt][3]);
            }
            int kbB = ks * 16 + (((l >> 3) & 1) << 3);
            uint32_t bh[4][4], bl[4][4];
            #pragma unroll
            for (int g2 = 0; g2 < 4; g2++) {
                int nn = nw + g2 * 16 + (l & 7) + ((l >> 4) << 3);
                uint32_t addr = bB + swa(nn, kbB);
                ldsm_x4(addr, bh[g2][0], bh[g2][1], bh[g2][2], bh[g2][3]);
                ldsm_x4(addr + 32768u, bl[g2][0], bl[g2][1], bl[g2][2], bl[g2][3]);
            }
            // ---- 48 MMAs from registers: AhBh + AlBh + AhBl ----
            #pragma unroll
            for (int g2 = 0; g2 < 4; g2++) {
                #pragma unroll
                for (int mt = 0; mt < 2; mt++) {
                    mma_bf16(acc[mt][2 * g2 + 0], ah[mt], bh[g2][0], bh[g2][1]);
                    mma_bf16(acc[mt][2 * g2 + 1], ah[mt], bh[g2][2], bh[g2][3]);
                    mma_bf16(acc[mt][2 * g2 + 0], al[mt], bh[g2][0], bh[g2][1]);
                    mma_bf16(acc[mt][2 * g2 + 1], al[mt], bh[g2][2], bh[g2][3]);
                    mma_bf16(acc[mt][2 * g2 + 0], ah[mt], bl[g2][0], bl[g2][1]);
                    mma_bf16(acc[mt][2 * g2 + 1], ah[mt], bl[g2][2], bl[g2][3]);
                }
            }
        }
    }

    // epilogue: D fragment layout (m16n8): rows g, g+8; cols 2t, 2t+1
    int g = l >> 2, t2 = (l & 3) * 2;
    #pragma unroll
    for (int mt = 0; mt < 2; mt++) {
        #pragma unroll
        for (int nt = 0; nt < 8; nt++) {
            int col = nw + nt * 8 + t2;
            float b0 = sbias[col], b1 = sbias[col + 1];
            int r1 = row0 + mw + mt * 16 + g;
            int r2 = r1 + 8;
            float o0 = acc[mt][nt][0] + b0, o1 = acc[mt][nt][1] + b1;
            float o2 = acc[mt][nt][2] + b0, o3 = acc[mt][nt][3] + b1;
            if (do_relu) {
                o0 = fmaxf(o0, 0.f); o1 = fmaxf(o1, 0.f);
                o2 = fmaxf(o2, 0.f); o3 = fmaxf(o3, 0.f);
            }
            if (r1 < n) *(float2*)(out + (size_t)r1 * D + col) = make_float2(o0, o1);
            if (r2 < n) *(float2*)(out + (size_t)r2 * D + col) = make_float2(o2, o3);
        }
    }
}

// ---------------- host launcher ----------------
extern "C" void kernel_launch(void* const* d_in, const int* in_sizes, int n_in,
                              void* d_out, int out_size) {
    const float* x  = (const float*)d_in[0];
    const void*  ei = d_in[1];
    const float* Wl = (const float*)d_in[2];
    const float* bl = (const float*)d_in[3];
    const float* Wr = (const float*)d_in[4];
    float* out = (float*)d_out;

    int n = in_sizes[0] / D;
    int E = in_sizes[1] / 2;
    int L = in_sizes[2] / (D * D);

    void* pbuf = nullptr;
    cudaGetSymbolAddress(&pbuf, g_buf);
    float* buf = (float*)pbuf;
    void* pdeg = nullptr;
    cudaGetSymbolAddress(&pdeg, g_degi);

    const int GEMM_SMEM = 196608 + 512;
    cudaFuncSetAttribute(k_gemm, cudaFuncAttributeMaxDynamicSharedMemorySize, GEMM_SMEM);

    // CSR build (once per call; dtype detect inlined per-warp in count/fill)
    cudaMemsetAsync(pdeg, 0, (size_t)n * sizeof(int));
    k_count<<<(E + 255) / 256, 256>>>(ei, E);
    int nb_s = (n + SCAN_B - 1) / SCAN_B;
    k_scan1<<<nb_s, SCAN_B>>>(n);
    k_scan3<<<nb_s, SCAN_B>>>(n, E, nb_s);
    k_fill<<<(E + 255) / 256, 256>>>(ei, E);

    // weight split/transpose/swizzle (once per call)
    int wtot = L << 15;
    k_prep_w<<<(wtot + 255) / 256, 256>>>(Wl, Wr, L);

    int nb = (n + 127) / 128;
    const float* cur = x;
    for (int l = 0; l < L; l++) {
        k_gather<<<(n + 7) / 8, 256>>>(cur, n);
        float* o = (l % 2 == 0) ? out : buf;   // L=5 -> final layer lands in out
        k_gemm<<<nb, 256, GEMM_SMEM>>>(cur, bl + (size_t)l * D, o, n, l, l < L - 1 ? 1 : 0);
        cur = o;
    }
    if (cur != out) {
        cudaMemcpyAsync(out, cur, (size_t)n * D * sizeof(float), cudaMemcpyDeviceToDevice);
    }
}

// round 13
// speedup vs baseline: 2.3680x; 1.0200x over previous
#include <cuda_runtime.h>
#include <cuda_bf16.h>
#include <cstdint>

#define D 128
#define NMAX 50000
#define EMAX 600000
#define LMAX 5
#define SCAN_B 256
#define NBLK ((NMAX + SCAN_B - 1) / SCAN_B)   // 196
#define MT 192                                 // M tile rows per CTA
#define RPW 24                                 // rows per warp in A convert

// ---------------- device scratch (no allocation allowed) ----------------
__device__ float g_aggr[NMAX * D];          // mean-aggregated features
__device__ float g_buf[NMAX * D];           // ping-pong activations
__device__ float g_inv[NMAX];               // 1/max(deg,1)
__device__ int   g_degi[NMAX];
__device__ int   g_rowptr[NMAX + 1];
__device__ int   g_cursor[NMAX];
__device__ int   g_tmp[NMAX];               // block-local inclusive scans
__device__ int   g_bsum[NBLK + 1];
__device__ int   g_srcs[EMAX];              // CSR: src node per (dst-sorted) edge
// weights pre-split (hi/lo bf16), transposed to [n][k], pre-swizzled:
// [layer][phase][split] blocks of 16384 bf16 (32KB each)
__device__ __nv_bfloat16 g_Bsw[LMAX * 2 * 2 * 16384];

// Bank-conflict-free swizzle for [row][k] bf16 tiles, 256B/row (128 k).
__device__ __forceinline__ uint32_t swa(int r, int k) {
    return (uint32_t)(r * 256 + ((((k >> 3) ^ (r & 7)) << 4)) + ((k & 7) << 1));
}

__device__ __forceinline__ uint32_t smem_u32(const void* p) {
    uint32_t a;
    asm("{ .reg .u64 t; cvta.to.shared.u64 t, %1; cvt.u32.u64 %0, t; }" : "=r"(a) : "l"(p));
    return a;
}

__device__ __forceinline__ uint32_t pack_bf16x2(float a, float b) {
    __nv_bfloat162 t = __floats2bfloat162_rn(a, b);
    return *reinterpret_cast<uint32_t*>(&t);
}

__device__ __forceinline__ void ldsm_x4(uint32_t addr, uint32_t& r0, uint32_t& r1,
                                        uint32_t& r2, uint32_t& r3) {
    asm volatile("ldmatrix.sync.aligned.m8n8.x4.shared.b16 {%0,%1,%2,%3}, [%4];"
                 : "=r"(r0), "=r"(r1), "=r"(r2), "=r"(r3) : "r"(addr));
}

__device__ __forceinline__ void mma_bf16(float* c, const uint32_t* a,
                                         uint32_t b0, uint32_t b1) {
    asm volatile(
        "mma.sync.aligned.m16n8k16.row.col.f32.bf16.bf16.f32 "
        "{%0,%1,%2,%3}, {%4,%5,%6,%7}, {%8,%9}, {%0,%1,%2,%3};"
        : "+f"(c[0]), "+f"(c[1]), "+f"(c[2]), "+f"(c[3])
        : "r"(a[0]), "r"(a[1]), "r"(a[2]), "r"(a[3]), "r"(b0), "r"(b1));
}

#define CP_ASYNC16(dst, src) \
    asm volatile("cp.async.cg.shared.global [%0], [%1], 16;" :: "r"(dst), "l"(src) : "memory")
#define CP_COMMIT() asm volatile("cp.async.commit_group;" ::: "memory")
#define CP_WAIT1()  asm volatile("cp.async.wait_group 1;" ::: "memory")
#define CP_WAIT0()  asm volatile("cp.async.wait_group 0;" ::: "memory")

// warp-local dtype detect: int64 indices in [0,50000) -> high words all zero.
__device__ __forceinline__ int warp_is64(const int* ei32) {
    int lane = threadIdx.x & 31;
    int v = ei32[2 * lane + 1];
    return __all_sync(0xffffffffu, v == 0);
}

// ---------------- CSR build ----------------
__global__ void k_count(const void* ei, int E) {
    int is64 = warp_is64((const int*)ei);
    int i = blockIdx.x * blockDim.x + threadIdx.x;
    if (i >= E) return;
    int d = is64 ? (int)((const long long*)ei)[(long long)E + i]
                 : ((const int*)ei)[(long long)E + i];
    atomicAdd(&g_degi[d], 1);
}

__device__ __forceinline__ int block_incl_scan(int v, int* warp_s) {
    int lane = threadIdx.x & 31, wid = threadIdx.x >> 5;
    #pragma unroll
    for (int off = 1; off < 32; off <<= 1) {
        int t = __shfl_up_sync(0xffffffffu, v, off);
        if (lane >= off) v += t;
    }
    if (lane == 31) warp_s[wid] = v;
    __syncthreads();
    if (wid == 0) {
        int w = (lane < (int)(blockDim.x >> 5)) ? warp_s[lane] : 0;
        #pragma unroll
        for (int off = 1; off < 32; off <<= 1) {
            int t = __shfl_up_sync(0xffffffffu, w, off);
            if (lane >= off) w += t;
        }
        warp_s[lane] = w;
    }
    __syncthreads();
    if (wid > 0) v += warp_s[wid - 1];
    return v;
}

__global__ void k_scan1(int n) {
    __shared__ int ws[32];
    int i = blockIdx.x * SCAN_B + threadIdx.x;
    int v = (i < n) ? g_degi[i] : 0;
    int incl = block_incl_scan(v, ws);
    if (i < n) g_tmp[i] = incl;
    if (threadIdx.x == SCAN_B - 1) g_bsum[blockIdx.x] = incl;
}
__global__ void k_scan3(int n, int E, int nb) {
    __shared__ int red[SCAN_B / 32];
    int tid = threadIdx.x, lane = tid & 31, wid = tid >> 5;
    int bid = blockIdx.x;
    int v = (tid < bid && tid < nb) ? g_bsum[tid] : 0;
    #pragma unroll
    for (int off = 16; off > 0; off >>= 1) v += __shfl_down_sync(0xffffffffu, v, off);
    if (lane == 0) red[wid] = v;
    __syncthreads();
    if (tid == 0) {
        int s = 0;
        #pragma unroll
        for (int w = 0; w < SCAN_B / 32; w++) s += red[w];
        red[0] = s;
    }
    __syncthreads();
    int boff = red[0];
    int i = bid * SCAN_B + tid;
    if (i < n) {
        int dg = g_degi[i];
        int excl = g_tmp[i] - dg + boff;
        g_rowptr[i] = excl;
        g_cursor[i] = excl;
        g_inv[i] = 1.0f / fmaxf((float)dg, 1.0f);
    }
    if (i == 0) g_rowptr[n] = E;
}

__global__ void k_fill(const void* ei, int E) {
    int is64 = warp_is64((const int*)ei);
    int i = blockIdx.x * blockDim.x + threadIdx.x;
    if (i >= E) return;
    int s, d;
    if (is64) {
        s = (int)((const long long*)ei)[i];
        d = (int)((const long long*)ei)[(long long)E + i];
    } else {
        s = ((const int*)ei)[i];
        d = ((const int*)ei)[(long long)E + i];
    }
    int pos = atomicAdd(&g_cursor[d], 1);
    g_srcs[pos] = s;
}

// ---------------- mean aggregation: warp per node (CSR gather) ----------------
__global__ void k_gather(const float* __restrict__ x, int n) {
    int w = (blockIdx.x * blockDim.x + threadIdx.x) >> 5;
    int lane = threadIdx.x & 31;
    if (w >= n) return;
    int b = g_rowptr[w], e = g_rowptr[w + 1];
    float4 acc = make_float4(0.f, 0.f, 0.f, 0.f);
    for (int j = b; j < e; j++) {
        int s = g_srcs[j];  // warp-uniform
        float4 v = ((const float4*)(x + (size_t)s * D))[lane];
        acc.x += v.x; acc.y += v.y; acc.z += v.z; acc.w += v.w;
    }
    float iv = g_inv[w];
    acc.x *= iv; acc.y *= iv; acc.z *= iv; acc.w *= iv;
    ((float4*)(g_aggr + (size_t)w * D))[lane] = acc;
}

// ---------------- weight prep: split bf16 hi/lo, transpose to [n][k], swizzle ---
__global__ void k_prep_w(const float* __restrict__ Wl, const float* __restrict__ Wr, int L) {
    int idx = blockIdx.x * blockDim.x + threadIdx.x;
    if (idx >= (L << 15)) return;          // L*2*128*128
    int k  = idx & 127;
    int nn = (idx >> 7) & 127;
    int ph = (idx >> 14) & 1;
    int l  = idx >> 15;
    float w = (ph == 0) ? Wl[((size_t)l * D + k) * D + nn]
                        : Wr[((size_t)l * D + k) * D + nn];
    __nv_bfloat16 h = __float2bfloat16(w);
    float r = w - __bfloat162float(h);
    size_t base = ((size_t)l * 2 + ph) * 2 * 16384;   // bf16 elements
    uint32_t off = swa(nn, k) >> 1;                   // bf16 index within 32KB tile
    g_Bsw[base + off] = h;
    g_Bsw[base + 16384 + off] = __float2bfloat16(r);
}

// ---------------- fused SAGE layer GEMM: ldmatrix + mma.sync bf16 3-pass -------
// out[192-tile] = aggr@Wl + x@Wr + b (+relu), fp32 accum in registers.
// M=192 tile: 261 CTAs = 1.76 waves (vs 2.64 at M=128); B traffic and
// per-CTA fixed costs amortized over 50% more rows.
// SMEM: A hi/lo 96KB + B0 64KB + B1 64KB + bias = ~224.5KB, 1 CTA/SM.
__global__ __launch_bounds__(256, 1)
void k_gemm(const float* __restrict__ x_in, const float* __restrict__ bias,
            float* __restrict__ out, int n, int layer, int do_relu) {
    extern __shared__ char sm[];
    char*  smA   = sm;                        // A hi (48KB) + A lo (48KB)
    float* sbias = (float*)(sm + 98304 + 131072);
    uint32_t sbA = smem_u32(smA);
    uint32_t sbB0 = smem_u32(sm + 98304);
    uint32_t sbB1 = smem_u32(sm + 98304 + 65536);

    int tid = threadIdx.x, wid = tid >> 5, l = tid & 31;
    int row0 = blockIdx.x * MT;
    int mw = (wid & 3) * 48;            // warp M offset (3 x 16-row subtiles)
    int nw = (wid >> 2) * 64;           // warp N offset

    // prefetch both phases' pre-swizzled B (64KB each) via cp.async
    {
        const char* b0 = (const char*)(g_Bsw + ((size_t)layer * 2 + 0) * 2 * 16384);
        const char* b1 = (const char*)(g_Bsw + ((size_t)layer * 2 + 1) * 2 * 16384);
        #pragma unroll 4
        for (int i = tid; i < 4096; i += 256)
            CP_ASYNC16(sbB0 + i * 16, b0 + (size_t)i * 16);
        CP_COMMIT();
        #pragma unroll 4
        for (int i = tid; i < 4096; i += 256)
            CP_ASYNC16(sbB1 + i * 16, b1 + (size_t)i * 16);
        CP_COMMIT();
    }

    if (tid < 128) sbias[tid] = bias[tid];

    float acc[3][8][4];
    #pragma unroll
    for (int mt = 0; mt < 3; mt++)
        #pragma unroll
        for (int nt = 0; nt < 8; nt++)
            #pragma unroll
            for (int q = 0; q < 4; q++) acc[mt][nt][q] = 0.f;

    for (int ph = 0; ph < 2; ph++) {
        if (ph) __syncthreads();        // all warps done reading A of phase 0

        // A: load fp32 rows, split bf16 hi/lo, swizzled STS (conflict-free)
        {
            const float* amat = ph ? x_in : g_aggr;
            int k0 = l * 4;
            #pragma unroll 4
            for (int rr = 0; rr < RPW; rr++) {
                int r = wid * RPW + rr;
                int grow = row0 + r;
                float4 v = make_float4(0.f, 0.f, 0.f, 0.f);
                if (grow < n) v = ((const float4*)(amat + (size_t)grow * D))[l];
                float h0 = __bfloat162float(__float2bfloat16(v.x));
                float h1 = __bfloat162float(__float2bfloat16(v.y));
                float h2 = __bfloat162float(__float2bfloat16(v.z));
                float h3 = __bfloat162float(__float2bfloat16(v.w));
                uint2 hi = make_uint2(pack_bf16x2(h0, h1), pack_bf16x2(h2, h3));
                uint2 lo = make_uint2(pack_bf16x2(v.x - h0, v.y - h1),
                                      pack_bf16x2(v.z - h2, v.w - h3));
                uint32_t off = swa(r, k0);
                *(uint2*)(smA + off)         = hi;
                *(uint2*)(smA + 49152 + off) = lo;
            }
        }
        if (ph == 0) CP_WAIT1();        // B0 landed
        else         CP_WAIT0();        // B1 landed
        __syncthreads();

        uint32_t bB = ph ? sbB1 : sbB0;
        #pragma unroll
        for (int ks = 0; ks < 8; ks++) {
            // ---- load ALL fragments for this ks once ----
            int kbA = ks * 16 + ((l >> 4) << 3);
            uint32_t ah[3][4], al[3][4];
            #pragma unroll
            for (int mt = 0; mt < 3; mt++) {
                uint32_t addr = sbA + swa(mw + mt * 16 + (l & 15), kbA);
                ldsm_x4(addr, ah[mt][0], ah[mt][1], ah[mt][2], ah[mt][3]);
                ldsm_x4(addr + 49152u, al[mt][0], al[mt][1], al[mt][2], al[mt][3]);
            }
            int kbB = ks * 16 + (((l >> 3) & 1) << 3);
            uint32_t bh[4][4], bl[4][4];
            #pragma unroll
            for (int g2 = 0; g2 < 4; g2++) {
                int nn = nw + g2 * 16 + (l & 7) + ((l >> 4) << 3);
                uint32_t addr = bB + swa(nn, kbB);
                ldsm_x4(addr, bh[g2][0], bh[g2][1], bh[g2][2], bh[g2][3]);
                ldsm_x4(addr + 32768u, bl[g2][0], bl[g2][1], bl[g2][2], bl[g2][3]);
            }
            // ---- 72 MMAs from registers: AhBh + AlBh + AhBl ----
            #pragma unroll
            for (int g2 = 0; g2 < 4; g2++) {
                #pragma unroll
                for (int mt = 0; mt < 3; mt++) {
                    mma_bf16(acc[mt][2 * g2 + 0], ah[mt], bh[g2][0], bh[g2][1]);
                    mma_bf16(acc[mt][2 * g2 + 1], ah[mt], bh[g2][2], bh[g2][3]);
                    mma_bf16(acc[mt][2 * g2 + 0], al[mt], bh[g2][0], bh[g2][1]);
                    mma_bf16(acc[mt][2 * g2 + 1], al[mt], bh[g2][2], bh[g2][3]);
                    mma_bf16(acc[mt][2 * g2 + 0], ah[mt], bl[g2][0], bl[g2][1]);
                    mma_bf16(acc[mt][2 * g2 + 1], ah[mt], bl[g2][2], bl[g2][3]);
                }
            }
        }
    }

    // epilogue: D fragment layout (m16n8): rows g, g+8; cols 2t, 2t+1
    int g = l >> 2, t2 = (l & 3) * 2;
    #pragma unroll
    for (int mt = 0; mt < 3; mt++) {
        #pragma unroll
        for (int nt = 0; nt < 8; nt++) {
            int col = nw + nt * 8 + t2;
            float b0 = sbias[col], b1 = sbias[col + 1];
            int r1 = row0 + mw + mt * 16 + g;
            int r2 = r1 + 8;
            float o0 = acc[mt][nt][0] + b0, o1 = acc[mt][nt][1] + b1;
            float o2 = acc[mt][nt][2] + b0, o3 = acc[mt][nt][3] + b1;
            if (do_relu) {
                o0 = fmaxf(o0, 0.f); o1 = fmaxf(o1, 0.f);
                o2 = fmaxf(o2, 0.f); o3 = fmaxf(o3, 0.f);
            }
            if (r1 < n) *(float2*)(out + (size_t)r1 * D + col) = make_float2(o0, o1);
            if (r2 < n) *(float2*)(out + (size_t)r2 * D + col) = make_float2(o2, o3);
        }
    }
}

// ---------------- host launcher ----------------
extern "C" void kernel_launch(void* const* d_in, const int* in_sizes, int n_in,
                              void* d_out, int out_size) {
    const float* x  = (const float*)d_in[0];
    const void*  ei = d_in[1];
    const float* Wl = (const float*)d_in[2];
    const float* bl = (const float*)d_in[3];
    const float* Wr = (const float*)d_in[4];
    float* out = (float*)d_out;

    int n = in_sizes[0] / D;
    int E = in_sizes[1] / 2;
    int L = in_sizes[2] / (D * D);

    void* pbuf = nullptr;
    cudaGetSymbolAddress(&pbuf, g_buf);
    float* buf = (float*)pbuf;
    void* pdeg = nullptr;
    cudaGetSymbolAddress(&pdeg, g_degi);

    const int GEMM_SMEM = 98304 + 131072 + 512;   // 224.5KB
    cudaFuncSetAttribute(k_gemm, cudaFuncAttributeMaxDynamicSharedMemorySize, GEMM_SMEM);

    // CSR build (once per call; dtype detect inlined per-warp in count/fill)
    cudaMemsetAsync(pdeg, 0, (size_t)n * sizeof(int));
    k_count<<<(E + 255) / 256, 256>>>(ei, E);
    int nb_s = (n + SCAN_B - 1) / SCAN_B;
    k_scan1<<<nb_s, SCAN_B>>>(n);
    k_scan3<<<nb_s, SCAN_B>>>(n, E, nb_s);
    k_fill<<<(E + 255) / 256, 256>>>(ei, E);

    // weight split/transpose/swizzle (once per call)
    int wtot = L << 15;
    k_prep_w<<<(wtot + 255) / 256, 256>>>(Wl, Wr, L);

    int nb = (n + MT - 1) / MT;
    const float* cur = x;
    for (int l = 0; l < L; l++) {
        k_gather<<<(n + 7) / 8, 256>>>(cur, n);
        float* o = (l % 2 == 0) ? out : buf;   // L=5 -> final layer lands in out
        k_gemm<<<nb, 256, GEMM_SMEM>>>(cur, bl + (size_t)l * D, o, n, l, l < L - 1 ? 1 : 0);
        cur = o;
    }
    if (cur != out) {
        cudaMemcpyAsync(out, cur, (size_t)n * D * sizeof(float), cudaMemcpyDeviceToDevice);
    }
}